// round 1
// baseline (speedup 1.0000x reference)
#include <cuda_runtime.h>
#include <math.h>

// MicrotubuleAttention: B=1, T=2048, D_MODEL=2048, H=16, Hkv=4, D=128, RANK=32
// Pipeline:
//   Q = x@Wq, K = x@Wk, V = x@Wv, A = x@WA, Bm = x@WB       (sgemm128)
//   M = sigmoid(A @ Bm^T)                                    (gemm_nt_sigmoid, reused by all heads)
//   RoPE(Q), RoPE(K)
//   flash attention with bias = -(pol/4096 + gamma)*delta + gate*M, causal
//   out = AO @ Wo                                            (sgemm128)

#define T_SEQ 2048

// Scratch (no cudaMalloc allowed)
__device__ __align__(128) float g_Q [T_SEQ * 2048];
__device__ __align__(128) float g_K [T_SEQ * 512];
__device__ __align__(128) float g_V [T_SEQ * 512];
__device__ __align__(128) float g_A [T_SEQ * 32];
__device__ __align__(128) float g_Bp[T_SEQ * 32];
__device__ __align__(128) float g_M [T_SEQ * T_SEQ];
__device__ __align__(128) float g_AO[T_SEQ * 2048];

// ---------------------------------------------------------------------------
// Generic fp32 GEMM: C[M,N] = A[M,K] @ B[K,N], row-major.
// BM=BN=128, BK=8, 256 threads, 8x8 per thread. M mult of 128, K mult of 8,
// N only needs to be a multiple of 4 (guards on B loads / C stores).
// ---------------------------------------------------------------------------
__global__ __launch_bounds__(256) void sgemm128(const float* __restrict__ A,
                                                const float* __restrict__ B,
                                                float* __restrict__ C,
                                                int M, int N, int K) {
    __shared__ float As[8][128];
    __shared__ float Bs[8][128];
    const int tid  = threadIdx.x;
    const int tx   = tid & 15, ty = tid >> 4;
    const int row0 = blockIdx.y * 128;
    const int col0 = blockIdx.x * 128;
    const int a_row = tid >> 1;
    const int a_col = (tid & 1) * 4;
    const int b_row = tid >> 5;
    const int b_col = (tid & 31) * 4;

    float acc[8][8];
#pragma unroll
    for (int i = 0; i < 8; i++)
#pragma unroll
        for (int j = 0; j < 8; j++) acc[i][j] = 0.f;

    const float* Aptr = A + (size_t)(row0 + a_row) * K + a_col;

    for (int k0 = 0; k0 < K; k0 += 8) {
        float4 av = *(const float4*)(Aptr + k0);
        As[a_col + 0][a_row] = av.x;
        As[a_col + 1][a_row] = av.y;
        As[a_col + 2][a_row] = av.z;
        As[a_col + 3][a_row] = av.w;
        float4 bv = make_float4(0.f, 0.f, 0.f, 0.f);
        if (col0 + b_col < N)
            bv = *(const float4*)(B + (size_t)(k0 + b_row) * N + col0 + b_col);
        *(float4*)&Bs[b_row][b_col] = bv;
        __syncthreads();
#pragma unroll
        for (int k = 0; k < 8; k++) {
            float a[8], b[8];
            *(float4*)&a[0] = *(const float4*)&As[k][ty * 8];
            *(float4*)&a[4] = *(const float4*)&As[k][ty * 8 + 4];
            // column split {tx*4, 64+tx*4} keeps Bs reads conflict-free
            *(float4*)&b[0] = *(const float4*)&Bs[k][tx * 4];
            *(float4*)&b[4] = *(const float4*)&Bs[k][64 + tx * 4];
#pragma unroll
            for (int i = 0; i < 8; i++)
#pragma unroll
                for (int j = 0; j < 8; j++) acc[i][j] = fmaf(a[i], b[j], acc[i][j]);
        }
        __syncthreads();
    }

#pragma unroll
    for (int i = 0; i < 8; i++) {
        int r  = row0 + ty * 8 + i;
        int c0 = col0 + tx * 4;
        if (c0 < N)
            *(float4*)(C + (size_t)r * N + c0) =
                make_float4(acc[i][0], acc[i][1], acc[i][2], acc[i][3]);
        int c1 = col0 + 64 + tx * 4;
        if (c1 < N)
            *(float4*)(C + (size_t)r * N + c1) =
                make_float4(acc[i][4], acc[i][5], acc[i][6], acc[i][7]);
    }
}

// ---------------------------------------------------------------------------
// M[i,j] = sigmoid( sum_{r<32} A[i,r] * B[j,r] )   (A,B row-major T x 32)
// 64x64 tile per block, 256 threads, 4x4 per thread, K=32 in one shot.
// ---------------------------------------------------------------------------
__global__ __launch_bounds__(256) void gemm_nt_sigmoid(const float* __restrict__ A,
                                                       const float* __restrict__ B,
                                                       float* __restrict__ C, int T) {
    __shared__ float As[32][65];
    __shared__ float Bs[32][65];
    const int tid = threadIdx.x;
    const int i0 = blockIdx.y * 64, j0 = blockIdx.x * 64;
    for (int idx = tid; idx < 64 * 32; idx += 256) {
        int m = idx >> 5, r = idx & 31;
        As[r][m] = A[(size_t)(i0 + m) * 32 + r];
        Bs[r][m] = B[(size_t)(j0 + m) * 32 + r];
    }
    __syncthreads();
    const int tx = tid & 15, ty = tid >> 4;
    float acc[4][4] = {};
#pragma unroll
    for (int r = 0; r < 32; r++) {
        float a[4], b[4];
#pragma unroll
        for (int i = 0; i < 4; i++) { a[i] = As[r][ty * 4 + i]; b[i] = Bs[r][tx * 4 + i]; }
#pragma unroll
        for (int i = 0; i < 4; i++)
#pragma unroll
            for (int j = 0; j < 4; j++) acc[i][j] = fmaf(a[i], b[j], acc[i][j]);
    }
#pragma unroll
    for (int i = 0; i < 4; i++)
#pragma unroll
        for (int j = 0; j < 4; j++) {
            C[(size_t)(i0 + ty * 4 + i) * T + j0 + tx * 4 + j] =
                1.f / (1.f + __expf(-acc[i][j]));
        }
}

// ---------------------------------------------------------------------------
// RoPE in-place: X layout (T, H*128). d in [0,64): rotate (x[d], x[d+64]).
// ---------------------------------------------------------------------------
__global__ void rope_kernel(float* __restrict__ X, int T, int H) {
    int idx = blockIdx.x * blockDim.x + threadIdx.x;
    int total = T * H * 64;
    if (idx >= total) return;
    int d = idx & 63;
    int h = (idx >> 6) % H;
    int t = idx / (64 * H);
    float inv = 1.0f / powf(10000.0f, (float)(2 * d) * (1.0f / 128.0f));
    float ang = (float)t * inv;
    float s, c;
    sincosf(ang, &s, &c);
    float* p = X + (size_t)t * (H * 128) + h * 128 + d;
    float x1 = p[0], x2 = p[64];
    p[0]  = x1 * c - x2 * s;
    p[64] = x2 * c + x1 * s;
}

// ---------------------------------------------------------------------------
// Flash attention. Block = 64 query rows for one head. 8 warps, each warp owns
// 8 rows; lane owns key-cols {2l, 2l+1} in the S phase and d-cols {4l..4l+3}
// in the O phase. bias = -(pol/4096 + gamma)*delta + gate*M[i,j], causal.
// ---------------------------------------------------------------------------
__global__ __launch_bounds__(256, 1) void attn_kernel(
    const float* __restrict__ Q, const float* __restrict__ Kg,
    const float* __restrict__ Vg, const float* __restrict__ Mg,
    const float* __restrict__ pol_dir, const float* __restrict__ pol_gate,
    const float* __restrict__ gtp_gamma, float* __restrict__ O) {
    extern __shared__ float sm[];
    float* Qs = sm;                 // 64 x 128
    float* Ks = Qs + 64 * 128;      // 64 rows, stride 132 (pad: 2-way max on reads)
    float* Vs = Ks + 64 * 132;      // 64 x 128
    float* Ps = Vs + 64 * 128;      // 64 rows, stride 66

    const int h   = blockIdx.y;
    const int i0  = blockIdx.x * 64;
    const int kvh = h >> 2;
    const int tid = threadIdx.x;
    const int warp = tid >> 5, lane = tid & 31;
    const int rowbase = warp * 8;

    const float pol   = fminf(1.f, fmaxf(-1.f, pol_dir[h]));
    const float gamma = fmaxf(log1pf(__expf(gtp_gamma[h])), 1e-6f);
    const float gate  = 1.f / (1.f + __expf(-pol_gate[h]));
    const float coef  = -(pol * (1.f / 4096.f) + gamma);  // * delta
    const float inv_sqrt_d = 0.08838834764831845f;        // 1/sqrt(128)

    for (int idx = tid; idx < 64 * 128; idx += 256) {
        int r = idx >> 7, c = idx & 127;
        Qs[r * 128 + c] = Q[(size_t)(i0 + r) * 2048 + h * 128 + c];
    }

    float m_i[8], l_i[8], acc[8][4];
#pragma unroll
    for (int r = 0; r < 8; r++) {
        m_i[r] = -1e30f; l_i[r] = 0.f;
        acc[r][0] = acc[r][1] = acc[r][2] = acc[r][3] = 0.f;
    }

    for (int j0 = 0; j0 <= i0; j0 += 64) {
        __syncthreads();
        for (int idx = tid; idx < 64 * 128; idx += 256) {
            int j = idx >> 7, k = idx & 127;
            size_t g = (size_t)(j0 + j) * 512 + kvh * 128 + k;
            Ks[j * 132 + k] = Kg[g];
            Vs[j * 128 + k] = Vg[g];
        }
        __syncthreads();

        // ---- S = Q K^T ----
        float s0[8], s1[8];
#pragma unroll
        for (int r = 0; r < 8; r++) { s0[r] = 0.f; s1[r] = 0.f; }
        const float4* Ka = (const float4*)(Ks + (2 * lane) * 132);
        const float4* Kb = (const float4*)(Ks + (2 * lane + 1) * 132);
        const float4* Q4 = (const float4*)(Qs + rowbase * 128);
#pragma unroll 4
        for (int kk = 0; kk < 32; kk++) {
            float4 ka = Ka[kk];
            float4 kb = Kb[kk];
#pragma unroll
            for (int r = 0; r < 8; r++) {
                float4 q = Q4[r * 32 + kk];
                s0[r] = fmaf(q.x, ka.x, fmaf(q.y, ka.y, fmaf(q.z, ka.z, fmaf(q.w, ka.w, s0[r]))));
                s1[r] = fmaf(q.x, kb.x, fmaf(q.y, kb.y, fmaf(q.z, kb.z, fmaf(q.w, kb.w, s1[r]))));
            }
        }

        // ---- bias + mask + online softmax ----
        const int jga = j0 + 2 * lane, jgb = jga + 1;
#pragma unroll
        for (int r = 0; r < 8; r++) {
            const int ig = i0 + rowbase + r;
            float v0 = -1e30f, v1 = -1e30f;
            if (jga <= ig) {
                float dd = (float)(ig - jga);
                v0 = fmaf(s0[r], inv_sqrt_d,
                          fmaf(coef, dd, gate * Mg[(size_t)ig * 2048 + jga]));
            }
            if (jgb <= ig) {
                float dd = (float)(ig - jgb);
                v1 = fmaf(s1[r], inv_sqrt_d,
                          fmaf(coef, dd, gate * Mg[(size_t)ig * 2048 + jgb]));
            }
            float mx = fmaxf(v0, v1);
#pragma unroll
            for (int o = 16; o > 0; o >>= 1)
                mx = fmaxf(mx, __shfl_xor_sync(0xffffffffu, mx, o));
            float mnew  = fmaxf(m_i[r], mx);
            float p0    = __expf(v0 - mnew);
            float p1    = __expf(v1 - mnew);
            float alpha = __expf(m_i[r] - mnew);
            m_i[r] = mnew;
            float ps = p0 + p1;
#pragma unroll
            for (int o = 16; o > 0; o >>= 1)
                ps += __shfl_xor_sync(0xffffffffu, ps, o);
            l_i[r] = l_i[r] * alpha + ps;
            acc[r][0] *= alpha; acc[r][1] *= alpha;
            acc[r][2] *= alpha; acc[r][3] *= alpha;
            Ps[(rowbase + r) * 66 + 2 * lane]     = p0;
            Ps[(rowbase + r) * 66 + 2 * lane + 1] = p1;
        }
        __syncwarp();

        // ---- O += P V ----
        const float4* V4 = (const float4*)Vs;
#pragma unroll 2
        for (int j = 0; j < 64; j++) {
            float4 v = V4[j * 32 + lane];
#pragma unroll
            for (int r = 0; r < 8; r++) {
                float p = Ps[(rowbase + r) * 66 + j];
                acc[r][0] = fmaf(p, v.x, acc[r][0]);
                acc[r][1] = fmaf(p, v.y, acc[r][1]);
                acc[r][2] = fmaf(p, v.z, acc[r][2]);
                acc[r][3] = fmaf(p, v.w, acc[r][3]);
            }
        }
    }

#pragma unroll
    for (int r = 0; r < 8; r++) {
        float inv_l = 1.f / l_i[r];
        int ig = i0 + rowbase + r;
        *(float4*)(O + (size_t)ig * 2048 + h * 128 + 4 * lane) =
            make_float4(acc[r][0] * inv_l, acc[r][1] * inv_l,
                        acc[r][2] * inv_l, acc[r][3] * inv_l);
    }
}

// ---------------------------------------------------------------------------

extern "C" void kernel_launch(void* const* d_in, const int* in_sizes, int n_in,
                              void* d_out, int out_size) {
    const float* x         = (const float*)d_in[0];
    const float* Wq        = (const float*)d_in[1];
    const float* Wk        = (const float*)d_in[2];
    const float* Wv        = (const float*)d_in[3];
    const float* Wo        = (const float*)d_in[4];
    const float* pol_dir   = (const float*)d_in[5];
    const float* pol_WA    = (const float*)d_in[6];
    const float* pol_WB    = (const float*)d_in[7];
    const float* pol_gate  = (const float*)d_in[8];
    const float* gtp_gamma = (const float*)d_in[9];
    float* out = (float*)d_out;

    float *Q, *K, *V, *A, *Bp, *M, *AO;
    cudaGetSymbolAddress((void**)&Q,  g_Q);
    cudaGetSymbolAddress((void**)&K,  g_K);
    cudaGetSymbolAddress((void**)&V,  g_V);
    cudaGetSymbolAddress((void**)&A,  g_A);
    cudaGetSymbolAddress((void**)&Bp, g_Bp);
    cudaGetSymbolAddress((void**)&M,  g_M);
    cudaGetSymbolAddress((void**)&AO, g_AO);

    // Projections
    sgemm128<<<dim3(16, 16), 256>>>(x, Wq,     Q,  2048, 2048, 2048);
    sgemm128<<<dim3(4, 16),  256>>>(x, Wk,     K,  2048, 512,  2048);
    sgemm128<<<dim3(4, 16),  256>>>(x, Wv,     V,  2048, 512,  2048);
    sgemm128<<<dim3(1, 16),  256>>>(x, pol_WA, A,  2048, 32,   2048);
    sgemm128<<<dim3(1, 16),  256>>>(x, pol_WB, Bp, 2048, 32,   2048);

    // Head-independent modulation matrix (shared by all 16 heads)
    gemm_nt_sigmoid<<<dim3(32, 32), 256>>>(A, Bp, M, T_SEQ);

    // RoPE
    rope_kernel<<<(T_SEQ * 16 * 64 + 255) / 256, 256>>>(Q, T_SEQ, 16);
    rope_kernel<<<(T_SEQ * 4 * 64 + 255) / 256,  256>>>(K, T_SEQ, 4);

    // Flash attention
    const int attn_smem = (64 * 128 + 64 * 132 + 64 * 128 + 64 * 66) * 4;  // 116224 B
    cudaFuncSetAttribute(attn_kernel, cudaFuncAttributeMaxDynamicSharedMemorySize,
                         attn_smem);
    attn_kernel<<<dim3(32, 16), 256, attn_smem>>>(Q, K, V, M, pol_dir, pol_gate,
                                                  gtp_gamma, AO);

    // Output projection
    sgemm128<<<dim3(16, 16), 256>>>(AO, Wo, out, 2048, 2048, 2048);
}

// round 11
// speedup vs baseline: 1.6839x; 1.6839x over previous
#include <cuda_runtime.h>
#include <math.h>

// MicrotubuleAttention: B=1, T=2048, D_MODEL=2048, H=16, Hkv=4, D=128, RANK=32

#define T_SEQ 2048

// Scratch (no cudaMalloc allowed)
__device__ __align__(128) float g_Q [T_SEQ * 2048];
__device__ __align__(128) float g_K [T_SEQ * 512];
__device__ __align__(128) float g_V [T_SEQ * 512];
__device__ __align__(128) float g_A [T_SEQ * 32];
__device__ __align__(128) float g_Bp[T_SEQ * 32];
__device__ __align__(128) float g_M [T_SEQ * T_SEQ];
__device__ __align__(128) float g_AO[T_SEQ * 2048];

// ---------------------------------------------------------------------------
// Shared fp32 GEMM body: C[.,N] tile (row0,col0) = A[M,K] @ B[K,N].
// BM=BN=128, BK=8, 256 threads, 8x8 per thread, register-prefetch double
// buffering. If DO_ROPE, the 128-wide tile is one head (col0 % 128 == 0) and
// thread accumulators (j, j+4) hold the RoPE pair (d, d+64): rotate in
// registers before the store (accurate sincosf; angles reach ~2047 rad).
// ---------------------------------------------------------------------------
template <bool DO_ROPE>
__device__ __forceinline__ void sgemm_body(const float* __restrict__ A,
                                           const float* __restrict__ B,
                                           float* __restrict__ C,
                                           int N, int K, int row0, int col0) {
    __shared__ float As[8][128];
    __shared__ float Bs[8][128];
    const int tid  = threadIdx.x;
    const int tx   = tid & 15, ty = tid >> 4;
    const int a_row = tid >> 1;
    const int a_col = (tid & 1) * 4;
    const int b_row = tid >> 5;
    const int b_col = (tid & 31) * 4;

    float acc[8][8];
#pragma unroll
    for (int i = 0; i < 8; i++)
#pragma unroll
        for (int j = 0; j < 8; j++) acc[i][j] = 0.f;

    const float* Aptr = A + (size_t)(row0 + a_row) * K + a_col;
    const float* Bptr = B + (size_t)b_row * N + col0 + b_col;

    float4 av = *(const float4*)(Aptr);
    float4 bv = *(const float4*)(Bptr);

    for (int k0 = 0; k0 < K; k0 += 8) {
        As[a_col + 0][a_row] = av.x;
        As[a_col + 1][a_row] = av.y;
        As[a_col + 2][a_row] = av.z;
        As[a_col + 3][a_row] = av.w;
        *(float4*)&Bs[b_row][b_col] = bv;
        __syncthreads();
        if (k0 + 8 < K) {
            av = *(const float4*)(Aptr + k0 + 8);
            bv = *(const float4*)(Bptr + (size_t)(k0 + 8) * N);
        }
#pragma unroll
        for (int k = 0; k < 8; k++) {
            float a[8], b[8];
            *(float4*)&a[0] = *(const float4*)&As[k][ty * 8];
            *(float4*)&a[4] = *(const float4*)&As[k][ty * 8 + 4];
            *(float4*)&b[0] = *(const float4*)&Bs[k][tx * 4];
            *(float4*)&b[4] = *(const float4*)&Bs[k][64 + tx * 4];
#pragma unroll
            for (int i = 0; i < 8; i++)
#pragma unroll
                for (int j = 0; j < 8; j++) acc[i][j] = fmaf(a[i], b[j], acc[i][j]);
        }
        __syncthreads();
    }

    if (DO_ROPE) {
        // dims d = tx*4+j (j<4) pair with d+64 held in acc[i][j+4].
        float invf[4];
#pragma unroll
        for (int j = 0; j < 4; j++) {
            invf[j] = exp2f(-(float)(2 * (tx * 4 + j)) * (1.0f / 128.0f)
                            * 13.287712379549449f);  // log2(10000)
        }
#pragma unroll
        for (int i = 0; i < 8; i++) {
            float t = (float)(row0 + ty * 8 + i);
#pragma unroll
            for (int j = 0; j < 4; j++) {
                float s, c;
                sincosf(t * invf[j], &s, &c);   // accurate: angle up to ~2047 rad
                float x1 = acc[i][j], x2 = acc[i][j + 4];
                acc[i][j]     = x1 * c - x2 * s;
                acc[i][j + 4] = x2 * c + x1 * s;
            }
        }
    }

#pragma unroll
    for (int i = 0; i < 8; i++) {
        int r = row0 + ty * 8 + i;
        *(float4*)(C + (size_t)r * N + col0 + tx * 4) =
            make_float4(acc[i][0], acc[i][1], acc[i][2], acc[i][3]);
        *(float4*)(C + (size_t)r * N + col0 + 64 + tx * 4) =
            make_float4(acc[i][4], acc[i][5], acc[i][6], acc[i][7]);
    }
}

// ---------------------------------------------------------------------------
// Rank-32 projection body: A = x@WA, Bp = x@WB (both 2048x32), 32 rows/block.
// ---------------------------------------------------------------------------
__device__ __forceinline__ void ab_body(const float* __restrict__ x,
                                        const float* __restrict__ WA,
                                        const float* __restrict__ WB,
                                        float* __restrict__ Ap,
                                        float* __restrict__ Bpp, int blk) {
    __shared__ float Xs[32][33];
    __shared__ float Ws[32][64];
    const int tid = threadIdx.x;
    const int tx = tid & 15, ty = tid >> 4;
    const int row0 = blk * 32;

    float acc[2][4] = {};

    for (int k0 = 0; k0 < 2048; k0 += 32) {
        {
            int idx = tid * 4;
            int r = idx >> 5, c = idx & 31;
            float4 v = *(const float4*)(x + (size_t)(row0 + r) * 2048 + k0 + c);
            Xs[r][c] = v.x; Xs[r][c + 1] = v.y; Xs[r][c + 2] = v.z; Xs[r][c + 3] = v.w;
        }
        {
            int idx = tid * 4;
            int k = idx >> 5, j = idx & 31;
            *(float4*)&Ws[k][j]      = *(const float4*)(WA + (size_t)(k0 + k) * 32 + j);
            *(float4*)&Ws[k][32 + j] = *(const float4*)(WB + (size_t)(k0 + k) * 32 + j);
        }
        __syncthreads();
#pragma unroll
        for (int k = 0; k < 32; k++) {
            float a0 = Xs[ty * 2][k], a1 = Xs[ty * 2 + 1][k];
            float b[4];
            *(float4*)&b[0] = *(const float4*)&Ws[k][tx * 4];
#pragma unroll
            for (int j = 0; j < 4; j++) {
                acc[0][j] = fmaf(a0, b[j], acc[0][j]);
                acc[1][j] = fmaf(a1, b[j], acc[1][j]);
            }
        }
        __syncthreads();
    }

    const int col = tx * 4;
#pragma unroll
    for (int i = 0; i < 2; i++) {
        int r = row0 + ty * 2 + i;
        float4 v = make_float4(acc[i][0], acc[i][1], acc[i][2], acc[i][3]);
        if (col < 32) *(float4*)(Ap  + (size_t)r * 32 + col)      = v;
        else          *(float4*)(Bpp + (size_t)r * 32 + col - 32) = v;
    }
}

// Output projection (and any standalone full GEMM)
__global__ __launch_bounds__(256, 2) void sgemm128(const float* __restrict__ A,
                                                   const float* __restrict__ B,
                                                   float* __restrict__ C,
                                                   int N, int K) {
    sgemm_body<false>(A, B, C, N, K, blockIdx.y * 128, blockIdx.x * 128);
}

// Fused Q/K/V projection (RoPE fused on Q,K) + rank-32 A/Bp projections.
// bx<16 -> Q (N=2048), 16..19 -> K, 20..23 -> V, 24..27 -> ab blocks.
__global__ __launch_bounds__(256, 2) void sgemm_qkv(
    const float* __restrict__ x,
    const float* __restrict__ Wq, const float* __restrict__ Wk,
    const float* __restrict__ Wv,
    const float* __restrict__ WA, const float* __restrict__ WB,
    float* __restrict__ Q, float* __restrict__ K, float* __restrict__ V,
    float* __restrict__ Ap, float* __restrict__ Bpp) {
    const int bx = blockIdx.x;
    if (bx < 16) {
        sgemm_body<true>(x, Wq, Q, 2048, 2048, blockIdx.y * 128, bx * 128);
    } else if (bx < 20) {
        sgemm_body<true>(x, Wk, K, 512, 2048, blockIdx.y * 128, (bx - 16) * 128);
    } else if (bx < 24) {
        sgemm_body<false>(x, Wv, V, 512, 2048, blockIdx.y * 128, (bx - 20) * 128);
    } else {
        ab_body(x, WA, WB, Ap, Bpp, (bx - 24) * 16 + blockIdx.y);
    }
}

// ---------------------------------------------------------------------------
// M[i,j] = sigmoid( sum_{r<32} A[i,r] * B[j,r] )
// ---------------------------------------------------------------------------
__global__ __launch_bounds__(256) void gemm_nt_sigmoid(const float* __restrict__ A,
                                                       const float* __restrict__ B,
                                                       float* __restrict__ C, int T) {
    __shared__ float As[32][65];
    __shared__ float Bs[32][65];
    const int tid = threadIdx.x;
    const int i0 = blockIdx.y * 64, j0 = blockIdx.x * 64;
    for (int idx = tid; idx < 64 * 32; idx += 256) {
        int m = idx >> 5, r = idx & 31;
        As[r][m] = A[(size_t)(i0 + m) * 32 + r];
        Bs[r][m] = B[(size_t)(j0 + m) * 32 + r];
    }
    __syncthreads();
    const int tx = tid & 15, ty = tid >> 4;
    float acc[4][4] = {};
#pragma unroll
    for (int r = 0; r < 32; r++) {
        float a[4], b[4];
#pragma unroll
        for (int i = 0; i < 4; i++) { a[i] = As[r][ty * 4 + i]; b[i] = Bs[r][tx * 4 + i]; }
#pragma unroll
        for (int i = 0; i < 4; i++)
#pragma unroll
            for (int j = 0; j < 4; j++) acc[i][j] = fmaf(a[i], b[j], acc[i][j]);
    }
#pragma unroll
    for (int i = 0; i < 4; i++)
#pragma unroll
        for (int j = 0; j < 4; j++) {
            C[(size_t)(i0 + ty * 4 + i) * T + j0 + tx * 4 + j] =
                1.f / (1.f + __expf(-acc[i][j]));
        }
}

// ---------------------------------------------------------------------------
// Flash attention. Block = 128 query rows for one head. 8 warps x 16 rows.
// Lane l owns key cols {l, l+32} of the 64-key tile (conflict-free LDS on Ks,
// coalesced M loads). bias = -(pol/4096 + gamma)*delta + gate*M[i,j], causal.
// ---------------------------------------------------------------------------
__global__ __launch_bounds__(256, 1) void attn_kernel(
    const float* __restrict__ Q, const float* __restrict__ Kg,
    const float* __restrict__ Vg, const float* __restrict__ Mg,
    const float* __restrict__ pol_dir, const float* __restrict__ pol_gate,
    const float* __restrict__ gtp_gamma, float* __restrict__ O) {
    extern __shared__ float sm[];
    float* Qs = sm;                  // 128 x 128
    float* Ks = Qs + 128 * 128;      // 64 rows, stride 132 (lane-stride 132w: bank 4l, conflict-free)
    float* Vs = Ks + 64 * 132;       // 64 x 128
    float* Ps = Vs + 64 * 128;       // 128 rows, stride 66

    const int h   = blockIdx.y;
    const int i0  = (gridDim.x - 1 - blockIdx.x) * 128;  // longest blocks first
    const int kvh = h >> 2;
    const int tid = threadIdx.x;
    const int warp = tid >> 5, lane = tid & 31;
    const int rowbase = warp * 16;

    const float pol   = fminf(1.f, fmaxf(-1.f, pol_dir[h]));
    const float gamma = fmaxf(log1pf(__expf(gtp_gamma[h])), 1e-6f);
    const float gate  = 1.f / (1.f + __expf(-pol_gate[h]));
    const float coef  = -(pol * (1.f / 4096.f) + gamma);  // * delta
    const float inv_sqrt_d = 0.08838834764831845f;        // 1/sqrt(128)

    for (int idx = tid; idx < 128 * 128; idx += 256) {
        int r = idx >> 7, c = idx & 127;
        Qs[r * 128 + c] = Q[(size_t)(i0 + r) * 2048 + h * 128 + c];
    }

    float m_i[16], l_i[16], acc[16][4];
#pragma unroll
    for (int r = 0; r < 16; r++) {
        m_i[r] = -1e30f; l_i[r] = 0.f;
        acc[r][0] = acc[r][1] = acc[r][2] = acc[r][3] = 0.f;
    }

    // keys tile [j0, j0+64); need j up to i0+127 -> last tile j0 = i0+64
    for (int j0 = 0; j0 <= i0 + 64; j0 += 64) {
        __syncthreads();
        for (int idx = tid; idx < 64 * 128; idx += 256) {
            int j = idx >> 7, k = idx & 127;
            size_t g = (size_t)(j0 + j) * 512 + kvh * 128 + k;
            Ks[j * 132 + k] = Kg[g];
            Vs[j * 128 + k] = Vg[g];
        }
        __syncthreads();

        // ---- S = Q K^T ----  lane owns key rows {lane, lane+32}
        float s0[16], s1[16];
#pragma unroll
        for (int r = 0; r < 16; r++) { s0[r] = 0.f; s1[r] = 0.f; }
        const float4* Ka = (const float4*)(Ks + lane * 132);
        const float4* Kb = (const float4*)(Ks + (lane + 32) * 132);
        const float4* Q4 = (const float4*)(Qs + rowbase * 128);
#pragma unroll 4
        for (int kk = 0; kk < 32; kk++) {
            float4 ka = Ka[kk];
            float4 kb = Kb[kk];
#pragma unroll
            for (int r = 0; r < 16; r++) {
                float4 q = Q4[r * 32 + kk];
                s0[r] = fmaf(q.x, ka.x, fmaf(q.y, ka.y, fmaf(q.z, ka.z, fmaf(q.w, ka.w, s0[r]))));
                s1[r] = fmaf(q.x, kb.x, fmaf(q.y, kb.y, fmaf(q.z, kb.z, fmaf(q.w, kb.w, s1[r]))));
            }
        }

        // ---- bias + mask + online softmax ----
        const int jga = j0 + lane, jgb = j0 + lane + 32;
#pragma unroll
        for (int r = 0; r < 16; r++) {
            const int ig = i0 + rowbase + r;
            float v0 = -1e30f, v1 = -1e30f;
            if (jga <= ig) {
                float dd = (float)(ig - jga);
                v0 = fmaf(s0[r], inv_sqrt_d,
                          fmaf(coef, dd, gate * Mg[(size_t)ig * 2048 + jga]));
            }
            if (jgb <= ig) {
                float dd = (float)(ig - jgb);
                v1 = fmaf(s1[r], inv_sqrt_d,
                          fmaf(coef, dd, gate * Mg[(size_t)ig * 2048 + jgb]));
            }
            float mx = fmaxf(v0, v1);
#pragma unroll
            for (int o = 16; o > 0; o >>= 1)
                mx = fmaxf(mx, __shfl_xor_sync(0xffffffffu, mx, o));
            float mnew  = fmaxf(m_i[r], mx);
            float p0    = __expf(v0 - mnew);
            float p1    = __expf(v1 - mnew);
            float alpha = __expf(m_i[r] - mnew);
            m_i[r] = mnew;
            float ps = p0 + p1;
#pragma unroll
            for (int o = 16; o > 0; o >>= 1)
                ps += __shfl_xor_sync(0xffffffffu, ps, o);
            l_i[r] = l_i[r] * alpha + ps;
            acc[r][0] *= alpha; acc[r][1] *= alpha;
            acc[r][2] *= alpha; acc[r][3] *= alpha;
            Ps[(rowbase + r) * 66 + lane]      = p0;
            Ps[(rowbase + r) * 66 + 32 + lane] = p1;
        }
        __syncwarp();

        // ---- O += P V ----
        const float4* V4 = (const float4*)Vs;
#pragma unroll 2
        for (int j = 0; j < 64; j++) {
            float4 v = V4[j * 32 + lane];
#pragma unroll
            for (int r = 0; r < 16; r++) {
                float p = Ps[(rowbase + r) * 66 + j];
                acc[r][0] = fmaf(p, v.x, acc[r][0]);
                acc[r][1] = fmaf(p, v.y, acc[r][1]);
                acc[r][2] = fmaf(p, v.z, acc[r][2]);
                acc[r][3] = fmaf(p, v.w, acc[r][3]);
            }
        }
    }

#pragma unroll
    for (int r = 0; r < 16; r++) {
        float inv_l = 1.f / l_i[r];
        int ig = i0 + rowbase + r;
        *(float4*)(O + (size_t)ig * 2048 + h * 128 + 4 * lane) =
            make_float4(acc[r][0] * inv_l, acc[r][1] * inv_l,
                        acc[r][2] * inv_l, acc[r][3] * inv_l);
    }
}

// ---------------------------------------------------------------------------

extern "C" void kernel_launch(void* const* d_in, const int* in_sizes, int n_in,
                              void* d_out, int out_size) {
    const float* x         = (const float*)d_in[0];
    const float* Wq        = (const float*)d_in[1];
    const float* Wk        = (const float*)d_in[2];
    const float* Wv        = (const float*)d_in[3];
    const float* Wo        = (const float*)d_in[4];
    const float* pol_dir   = (const float*)d_in[5];
    const float* pol_WA    = (const float*)d_in[6];
    const float* pol_WB    = (const float*)d_in[7];
    const float* pol_gate  = (const float*)d_in[8];
    const float* gtp_gamma = (const float*)d_in[9];
    float* out = (float*)d_out;

    float *Q, *K, *V, *A, *Bp, *M, *AO;
    cudaGetSymbolAddress((void**)&Q,  g_Q);
    cudaGetSymbolAddress((void**)&K,  g_K);
    cudaGetSymbolAddress((void**)&V,  g_V);
    cudaGetSymbolAddress((void**)&A,  g_A);
    cudaGetSymbolAddress((void**)&Bp, g_Bp);
    cudaGetSymbolAddress((void**)&M,  g_M);
    cudaGetSymbolAddress((void**)&AO, g_AO);

    // Fused Q/K/V projection (RoPE fused) + rank-32 A/Bp projections
    sgemm_qkv<<<dim3(28, 16), 256>>>(x, Wq, Wk, Wv, pol_WA, pol_WB,
                                     Q, K, V, A, Bp);

    // Head-independent modulation matrix
    gemm_nt_sigmoid<<<dim3(32, 32), 256>>>(A, Bp, M, T_SEQ);

    // Flash attention: 128 q-rows per block
    const int attn_smem = (128 * 128 + 64 * 132 + 64 * 128 + 128 * 66) * 4;  // 165888 B
    cudaFuncSetAttribute(attn_kernel, cudaFuncAttributeMaxDynamicSharedMemorySize,
                         attn_smem);
    attn_kernel<<<dim3(16, 16), 256, attn_smem>>>(Q, K, V, M, pol_dir, pol_gate,
                                                  gtp_gamma, AO);

    // Output projection
    sgemm128<<<dim3(16, 16), 256>>>(AO, Wo, out, 2048, 2048);
}